// round 10
// baseline (speedup 1.0000x reference)
#include <cuda_runtime.h>
#include <cstdint>

// Problem shape (fixed by the dataset): B=512, S=1024, T=64
#define Bn 512
#define Sn 1024
#define Tn 64
#define WPB 8          // forward warps per block = independent batches/block
                       // (2 chain-warps per SMSP: mutual latency cover)
#define FWD_BLOCKS 64  // 64 blocks x 8 batches = 512
#define GOLD_BLOCKS 16 // gold on otherwise-idle SMs

typedef unsigned long long u64;

__device__ float g_z[Bn];
__device__ float g_sc[Bn];

__device__ __forceinline__ u64 ffma2(u64 a, u64 b, u64 c) {
    u64 d;
    asm("fma.rn.f32x2 %0, %1, %2, %3;" : "=l"(d) : "l"(a), "l"(b), "l"(c));
    return d;
}
__device__ __forceinline__ u64 fadd2(u64 a, u64 b) {
    u64 d;
    asm("add.rn.f32x2 %0, %1, %2;" : "=l"(d) : "l"(a), "l"(b));
    return d;
}
__device__ __forceinline__ u64 fmul2(u64 a, u64 b) {
    u64 d;
    asm("mul.rn.f32x2 %0, %1, %2;" : "=l"(d) : "l"(a), "l"(b));
    return d;
}
__device__ __forceinline__ u64 pk2(float a, float b) {
    u64 d;
    asm("mov.b64 %0, {%1,%2};" : "=l"(d) : "f"(a), "f"(b));
    return d;
}
__device__ __forceinline__ float2 upk(u64 p) {
    float2 r;
    asm("mov.b64 {%0,%1}, %2;" : "=f"(r.x), "=f"(r.y) : "l"(p));
    return r;
}

// ---------------------------------------------------------------------------
// Forward recursion (blocks 0..63), linear domain, ONE WARP PER BATCH:
//   s_{t+1}[j] = (sum_i s_t[i] * E[i][j]) * exp(e_t[j]),  E = exp(trans)
// 8 warps/block on 64 SMs -> 2 independent chain-warps per SMSP; each covers
// the other's STS/sync/LDS/tail latency with its FFMA2 stream. No block
// barriers in the recursion (warp-private smem + __syncwarp only).
// Thread c owns columns (2c, 2c+1). Renorm every 8 steps by 2^-ke from the
// exponent bits of s[0]. Gold scores: blocks 64..79 on idle SMs.
// ---------------------------------------------------------------------------
__global__ __launch_bounds__(32 * WPB, 1) void crf_fused(
    const float* __restrict__ em,    // [B, S, T]
    const int*   __restrict__ tags,  // [B, S]
    const float* __restrict__ mask,  // [B, S]
    const float* __restrict__ tr)    // [T, T]
{
    const int w    = threadIdx.x >> 5;
    const int lane = threadIdx.x & 31;

    if (blockIdx.x >= FWD_BLOCKS) {
        // ---------------- gold blocks: 8 warps, 4 batches per warp --------
        const int gw = (blockIdx.x - FWD_BLOCKS) * WPB + w;  // 0..127
        for (int k = 0; k < 4; k++) {
            const int b = gw * 4 + k;
            const int* tg = tags + b * Sn;
            const float* eb = em + (size_t)b * Sn * Tn;
            float acc = 0.0f;
            for (int sx = 1 + lane; sx < Sn; sx += 32) {
                int   t1  = __ldg(tg + sx);
                int   t0  = __ldg(tg + sx - 1);
                float mt  = __ldg(mask + b * Sn + sx);
                float emv = __ldg(eb + (size_t)sx * Tn + t1);
                float trv = __ldg(tr + t0 * Tn + t1);
                acc += (emv + trv) * mt;
            }
#pragma unroll
            for (int o = 16; o; o >>= 1)
                acc += __shfl_xor_sync(0xffffffffu, acc, o);
            if (lane == 0) g_sc[b] = acc;
        }
        return;
    }

    // ---------------- forward: warp w owns batch b ----------------
    const int c = lane;                        // column pair (2c, 2c+1)
    const int b = blockIdx.x * WPB + w;

    __shared__ __align__(16) u64 sbuf[WPB][2][32];  // double-buffered s pairs
    __shared__ float mrow[WPB][Sn];                 // mask (plain float)

    // Stage mask row (warp-private region; no block sync needed)
    for (int i = c; i < Sn; i += 32) mrow[w][i] = mask[b * Sn + i];

    // E register tiles: EA[p] = (E[2p][2c], E[2p+1][2c]), EB for col 2c+1
    u64 EA[32], EB[32];
#pragma unroll
    for (int p = 0; p < 32; p++) {
        EA[p] = pk2(__expf(tr[(2 * p) * Tn + 2 * c]),
                    __expf(tr[(2 * p + 1) * Tn + 2 * c]));
        EB[p] = pk2(__expf(tr[(2 * p) * Tn + 2 * c + 1]),
                    __expf(tr[(2 * p + 1) * Tn + 2 * c + 1]));
    }

    // Emission pipeline: raw float2 loaded 8 steps ahead, exp'd 2 ahead
    const float2* ep = (const float2*)(em + (size_t)b * Sn * Tn) + c;
    float2 eraw[8];
    u64    fbuf[4];
#pragma unroll
    for (int d = 0; d < 8; d++) eraw[d] = __ldg(ep + d * 32);
    fbuf[0] = pk2(__expf(eraw[0].x), __expf(eraw[0].y));
    fbuf[1] = pk2(__expf(eraw[1].x), __expf(eraw[1].y));

    u64 s    = pk2(1.0f, 1.0f);
    int offk = 0;
    __syncwarp();

    for (int tb = 0; tb < Sn; tb += 8) {
#pragma unroll
        for (int u = 0; u < 8; u++) {
            const int t   = tb + u;
            const int par = u & 1;

            // publish own pair; warp-local sync
            sbuf[w][par][c] = s;

            // independent refills fill the sync window
            float m = mrow[w][t];
            fbuf[(u + 2) & 3] =
                pk2(__expf(eraw[(u + 2) & 7].x), __expf(eraw[(u + 2) & 7].y));
            if (t + 8 < Sn) eraw[u] = __ldg(ep + (size_t)(t + 8) * 32);

            __syncwarp();

            // matvec for both columns: 16 LDS.128, 64 FFMA2 (8 acc chains)
            const u64* sv = &sbuf[w][par][0];
            u64 a0 = 0, a1 = 0, a2 = 0, a3 = 0;
            u64 b0 = 0, b1 = 0, b2 = 0, b3 = 0;
            u64 v0pair;
#pragma unroll
            for (int p = 0; p < 32; p += 4) {
                ulonglong2 x = *(const ulonglong2*)&sv[p];
                ulonglong2 y = *(const ulonglong2*)&sv[p + 2];
                if (p == 0) v0pair = x.x;
                a0 = ffma2(x.x, EA[p + 0], a0);
                b0 = ffma2(x.x, EB[p + 0], b0);
                a1 = ffma2(x.y, EA[p + 1], a1);
                b1 = ffma2(x.y, EB[p + 1], b1);
                a2 = ffma2(y.x, EA[p + 2], a2);
                b2 = ffma2(y.x, EB[p + 2], b2);
                a3 = ffma2(y.y, EA[p + 3], a3);
                b3 = ffma2(y.y, EB[p + 3], b3);
            }
            u64 sa = fadd2(fadd2(a0, a1), fadd2(a2, a3));
            u64 sb = fadd2(fadd2(b0, b1), fadd2(b2, b3));
            float2 fa = upk(sa), fb2 = upk(sb);
            u64 qf = fmul2(pk2(fa.x + fa.y, fb2.x + fb2.y), fbuf[u & 3]);

            // masked blend: s = m*qf + (1-m)*s
            float om = 1.0f - m;
            u64 sn = ffma2(pk2(om, om), s, fmul2(pk2(m, m), qf));

            // renorm every 8 steps by 2^-ke, ke from exponent of s[0]
            if (u == 7) {
                int ke = ((__float_as_int(upk(v0pair).x) >> 23) & 0xff) - 127;
                offk += ke;
                float sc = __int_as_float((127 - ke) << 23);
                sn = fmul2(sn, pk2(sc, sc));
            }
            s = sn;
        }
    }

    // z[b] = offk*ln2 + log(sum_j s[j])
    float2 sp = upk(s);
    float x = sp.x + sp.y;
#pragma unroll
    for (int o = 16; o; o >>= 1)
        x += __shfl_xor_sync(0xffffffffu, x, o);
    if (lane == 0) {
        double z = (double)offk * 0.6931471805599453 + (double)logf(x);
        g_z[b] = (float)z;
    }
}

// ---------------------------------------------------------------------------
// out = -mean(z - score)
// ---------------------------------------------------------------------------
__global__ __launch_bounds__(Bn) void crf_final(float* __restrict__ out)
{
    __shared__ float red[Bn];
    const int tid = threadIdx.x;
    red[tid] = g_z[tid] - g_sc[tid];
    __syncthreads();
    for (int st = Bn / 2; st; st >>= 1) {
        if (tid < st) red[tid] += red[tid + st];
        __syncthreads();
    }
    if (tid == 0) out[0] = -red[0] / (float)Bn;
}

extern "C" void kernel_launch(void* const* d_in, const int* in_sizes, int n_in,
                              void* d_out, int out_size)
{
    const float* em   = (const float*)d_in[0];  // emissions [B,S,T] f32
    const int*   tags = (const int*)  d_in[1];  // tags [B,S] i32
    const float* mask = (const float*)d_in[2];  // mask [B,S] f32
    const float* tr   = (const float*)d_in[3];  // transitions [T,T] f32

    crf_fused<<<FWD_BLOCKS + GOLD_BLOCKS, 32 * WPB>>>(em, tags, mask, tr);
    crf_final<<<1, Bn>>>((float*)d_out);
}

// round 11
// speedup vs baseline: 1.0048x; 1.0048x over previous
#include <cuda_runtime.h>
#include <cstdint>

// Problem shape (fixed by the dataset): B=512, S=1024, T=64
#define Bn 512
#define Sn 1024
#define Tn 64
#define WPB 8          // forward warps per block = independent batches/block
                       // (2 chain-warps per SMSP: mutual latency cover)
#define FWD_BLOCKS 64  // 64 blocks x 8 batches = 512
#define GOLD_BLOCKS 16 // gold on otherwise-idle SMs

typedef unsigned long long u64;

__device__ float g_z[Bn];
__device__ float g_sc[Bn];

__device__ __forceinline__ u64 ffma2(u64 a, u64 b, u64 c) {
    u64 d;
    asm("fma.rn.f32x2 %0, %1, %2, %3;" : "=l"(d) : "l"(a), "l"(b), "l"(c));
    return d;
}
__device__ __forceinline__ u64 fadd2(u64 a, u64 b) {
    u64 d;
    asm("add.rn.f32x2 %0, %1, %2;" : "=l"(d) : "l"(a), "l"(b));
    return d;
}
__device__ __forceinline__ u64 fmul2(u64 a, u64 b) {
    u64 d;
    asm("mul.rn.f32x2 %0, %1, %2;" : "=l"(d) : "l"(a), "l"(b));
    return d;
}
__device__ __forceinline__ u64 pk2(float a, float b) {
    u64 d;
    asm("mov.b64 %0, {%1,%2};" : "=l"(d) : "f"(a), "f"(b));
    return d;
}
__device__ __forceinline__ float2 upk(u64 p) {
    float2 r;
    asm("mov.b64 {%0,%1}, %2;" : "=f"(r.x), "=f"(r.y) : "l"(p));
    return r;
}

// ---------------------------------------------------------------------------
// Forward recursion (blocks 0..63), linear domain, ONE WARP PER BATCH:
//   s_{t+1}[j] = (sum_i s_t[i] * E[i][j]) * exp(e_t[j]),  E = exp(trans)
// 8 warps/block on 64 SMs -> 2 independent chain-warps per SMSP; each covers
// the other's STS/sync/LDS/tail latency with its FFMA2 stream. No block
// barriers in the recursion (warp-private smem + __syncwarp only).
// Thread c owns columns (2c, 2c+1). Renorm every 8 steps by 2^-ke from the
// exponent bits of s[0]. Gold scores: blocks 64..79 on idle SMs.
// ---------------------------------------------------------------------------
__global__ __launch_bounds__(32 * WPB, 1) void crf_fused(
    const float* __restrict__ em,    // [B, S, T]
    const int*   __restrict__ tags,  // [B, S]
    const float* __restrict__ mask,  // [B, S]
    const float* __restrict__ tr)    // [T, T]
{
    const int w    = threadIdx.x >> 5;
    const int lane = threadIdx.x & 31;

    if (blockIdx.x >= FWD_BLOCKS) {
        // ---------------- gold blocks: 8 warps, 4 batches per warp --------
        const int gw = (blockIdx.x - FWD_BLOCKS) * WPB + w;  // 0..127
        for (int k = 0; k < 4; k++) {
            const int b = gw * 4 + k;
            const int* tg = tags + b * Sn;
            const float* eb = em + (size_t)b * Sn * Tn;
            float acc = 0.0f;
            for (int sx = 1 + lane; sx < Sn; sx += 32) {
                int   t1  = __ldg(tg + sx);
                int   t0  = __ldg(tg + sx - 1);
                float mt  = __ldg(mask + b * Sn + sx);
                float emv = __ldg(eb + (size_t)sx * Tn + t1);
                float trv = __ldg(tr + t0 * Tn + t1);
                acc += (emv + trv) * mt;
            }
#pragma unroll
            for (int o = 16; o; o >>= 1)
                acc += __shfl_xor_sync(0xffffffffu, acc, o);
            if (lane == 0) g_sc[b] = acc;
        }
        return;
    }

    // ---------------- forward: warp w owns batch b ----------------
    const int c = lane;                        // column pair (2c, 2c+1)
    const int b = blockIdx.x * WPB + w;

    __shared__ __align__(16) u64 sbuf[WPB][2][32];  // double-buffered s pairs
    __shared__ float mrow[WPB][Sn];                 // mask (plain float)

    // Stage mask row (warp-private region; no block sync needed)
    for (int i = c; i < Sn; i += 32) mrow[w][i] = mask[b * Sn + i];

    // E register tiles: EA[p] = (E[2p][2c], E[2p+1][2c]), EB for col 2c+1
    u64 EA[32], EB[32];
#pragma unroll
    for (int p = 0; p < 32; p++) {
        EA[p] = pk2(__expf(tr[(2 * p) * Tn + 2 * c]),
                    __expf(tr[(2 * p + 1) * Tn + 2 * c]));
        EB[p] = pk2(__expf(tr[(2 * p) * Tn + 2 * c + 1]),
                    __expf(tr[(2 * p + 1) * Tn + 2 * c + 1]));
    }

    // Emission pipeline: raw float2 loaded 8 steps ahead, exp'd 2 ahead
    const float2* ep = (const float2*)(em + (size_t)b * Sn * Tn) + c;
    float2 eraw[8];
    u64    fbuf[4];
#pragma unroll
    for (int d = 0; d < 8; d++) eraw[d] = __ldg(ep + d * 32);
    fbuf[0] = pk2(__expf(eraw[0].x), __expf(eraw[0].y));
    fbuf[1] = pk2(__expf(eraw[1].x), __expf(eraw[1].y));

    u64 s    = pk2(1.0f, 1.0f);
    int offk = 0;
    __syncwarp();

    for (int tb = 0; tb < Sn; tb += 8) {
#pragma unroll
        for (int u = 0; u < 8; u++) {
            const int t   = tb + u;
            const int par = u & 1;

            // publish own pair; warp-local sync
            sbuf[w][par][c] = s;

            // independent refills fill the sync window
            float m = mrow[w][t];
            fbuf[(u + 2) & 3] =
                pk2(__expf(eraw[(u + 2) & 7].x), __expf(eraw[(u + 2) & 7].y));
            if (t + 8 < Sn) eraw[u] = __ldg(ep + (size_t)(t + 8) * 32);

            __syncwarp();

            // matvec for both columns: 16 LDS.128, 64 FFMA2 (8 acc chains)
            const u64* sv = &sbuf[w][par][0];
            u64 a0 = 0, a1 = 0, a2 = 0, a3 = 0;
            u64 b0 = 0, b1 = 0, b2 = 0, b3 = 0;
            u64 v0pair;
#pragma unroll
            for (int p = 0; p < 32; p += 4) {
                ulonglong2 x = *(const ulonglong2*)&sv[p];
                ulonglong2 y = *(const ulonglong2*)&sv[p + 2];
                if (p == 0) v0pair = x.x;
                a0 = ffma2(x.x, EA[p + 0], a0);
                b0 = ffma2(x.x, EB[p + 0], b0);
                a1 = ffma2(x.y, EA[p + 1], a1);
                b1 = ffma2(x.y, EB[p + 1], b1);
                a2 = ffma2(y.x, EA[p + 2], a2);
                b2 = ffma2(y.x, EB[p + 2], b2);
                a3 = ffma2(y.y, EA[p + 3], a3);
                b3 = ffma2(y.y, EB[p + 3], b3);
            }
            u64 sa = fadd2(fadd2(a0, a1), fadd2(a2, a3));
            u64 sb = fadd2(fadd2(b0, b1), fadd2(b2, b3));
            float2 fa = upk(sa), fb2 = upk(sb);
            u64 qf = fmul2(pk2(fa.x + fa.y, fb2.x + fb2.y), fbuf[u & 3]);

            // masked blend: s = m*qf + (1-m)*s
            float om = 1.0f - m;
            u64 sn = ffma2(pk2(om, om), s, fmul2(pk2(m, m), qf));

            // renorm every 8 steps by 2^-ke, ke from exponent of s[0]
            if (u == 7) {
                int ke = ((__float_as_int(upk(v0pair).x) >> 23) & 0xff) - 127;
                offk += ke;
                float sc = __int_as_float((127 - ke) << 23);
                sn = fmul2(sn, pk2(sc, sc));
            }
            s = sn;
        }
    }

    // z[b] = offk*ln2 + log(sum_j s[j])
    float2 sp = upk(s);
    float x = sp.x + sp.y;
#pragma unroll
    for (int o = 16; o; o >>= 1)
        x += __shfl_xor_sync(0xffffffffu, x, o);
    if (lane == 0) {
        double z = (double)offk * 0.6931471805599453 + (double)logf(x);
        g_z[b] = (float)z;
    }
}

// ---------------------------------------------------------------------------
// out = -mean(z - score)
// ---------------------------------------------------------------------------
__global__ __launch_bounds__(Bn) void crf_final(float* __restrict__ out)
{
    __shared__ float red[Bn];
    const int tid = threadIdx.x;
    red[tid] = g_z[tid] - g_sc[tid];
    __syncthreads();
    for (int st = Bn / 2; st; st >>= 1) {
        if (tid < st) red[tid] += red[tid + st];
        __syncthreads();
    }
    if (tid == 0) out[0] = -red[0] / (float)Bn;
}

extern "C" void kernel_launch(void* const* d_in, const int* in_sizes, int n_in,
                              void* d_out, int out_size)
{
    const float* em   = (const float*)d_in[0];  // emissions [B,S,T] f32
    const int*   tags = (const int*)  d_in[1];  // tags [B,S] i32
    const float* mask = (const float*)d_in[2];  // mask [B,S] f32
    const float* tr   = (const float*)d_in[3];  // transitions [T,T] f32

    crf_fused<<<FWD_BLOCKS + GOLD_BLOCKS, 32 * WPB>>>(em, tags, mask, tr);
    crf_final<<<1, Bn>>>((float*)d_out);
}

// round 12
// speedup vs baseline: 1.6001x; 1.5924x over previous
#include <cuda_runtime.h>
#include <cstdint>

// Problem shape (fixed by the dataset): B=512, S=1024, T=64
#define Bn 512
#define Sn 1024
#define Tn 64
#define WPB 4          // forward warps per block: one chain-warp per SMSP
#define FWD_BLOCKS 128 // blocks 0..127: forward (512 chains, 1/SMSP)
#define GOLD_BLOCKS 16 // blocks 128..143: gold scores on idle SMs

typedef unsigned long long u64;

__device__ float g_z[Bn];
__device__ float g_sc[Bn];

__device__ __forceinline__ u64 ffma2(u64 a, u64 b, u64 c) {
    u64 d;
    asm("fma.rn.f32x2 %0, %1, %2, %3;" : "=l"(d) : "l"(a), "l"(b), "l"(c));
    return d;
}
__device__ __forceinline__ u64 fadd2(u64 a, u64 b) {
    u64 d;
    asm("add.rn.f32x2 %0, %1, %2;" : "=l"(d) : "l"(a), "l"(b));
    return d;
}
__device__ __forceinline__ u64 fmul2(u64 a, u64 b) {
    u64 d;
    asm("mul.rn.f32x2 %0, %1, %2;" : "=l"(d) : "l"(a), "l"(b));
    return d;
}
__device__ __forceinline__ u64 pk2(float a, float b) {
    u64 d;
    asm("mov.b64 %0, {%1,%2};" : "=l"(d) : "f"(a), "f"(b));
    return d;
}
__device__ __forceinline__ float2 upk(u64 p) {
    float2 r;
    asm("mov.b64 {%0,%1}, %2;" : "=f"(r.x), "=f"(r.y) : "l"(p));
    return r;
}

// ---------------------------------------------------------------------------
// Forward recursion (blocks 0..127), linear domain, ONE WARP PER CHAIN,
// one chain-warp per SMSP (proven optimal geometry):
//   s_{t+1}[j] = (sum_i s_t[i] * E[i][j]) * exp(e_t[j]),  E = exp(trans)
// Thread c owns columns (2c, 2c+1). Per step: STS own pair; independent
// refills (mask LDS, emission exp MUFU, LDG 8-ahead) ride through the
// syncwarp window; 16 LDS.128 + 64 FFMA2 matvec; renorm every 8 steps by
// 2^-ke from the exponent bits of s[0].
// Gold scores (blocks 128..143) run on SMs the forward grid leaves idle.
// ---------------------------------------------------------------------------
__global__ __launch_bounds__(32 * WPB, 1) void crf_fused(
    const float* __restrict__ em,    // [B, S, T]
    const int*   __restrict__ tags,  // [B, S]
    const float* __restrict__ mask,  // [B, S]
    const float* __restrict__ tr)    // [T, T]
{
    const int w    = threadIdx.x >> 5;
    const int lane = threadIdx.x & 31;

    if (blockIdx.x >= FWD_BLOCKS) {
        // ------- gold blocks: 4 warps/block, 8 batches per warp -------
        const int gw = (blockIdx.x - FWD_BLOCKS) * WPB + w;  // 0..63
        for (int k = 0; k < 8; k++) {
            const int b = gw * 8 + k;
            const int* tg = tags + b * Sn;
            const float* eb = em + (size_t)b * Sn * Tn;
            float acc = 0.0f;
            for (int sx = 1 + lane; sx < Sn; sx += 32) {
                int   t1  = __ldg(tg + sx);
                int   t0  = __ldg(tg + sx - 1);
                float mt  = __ldg(mask + b * Sn + sx);
                float emv = __ldg(eb + (size_t)sx * Tn + t1);
                float trv = __ldg(tr + t0 * Tn + t1);
                acc += (emv + trv) * mt;
            }
#pragma unroll
            for (int o = 16; o; o >>= 1)
                acc += __shfl_xor_sync(0xffffffffu, acc, o);
            if (lane == 0) g_sc[b] = acc;
        }
        return;
    }

    // ---------------- forward: warp w owns batch b ----------------
    const int c = lane;                        // column pair (2c, 2c+1)
    const int b = blockIdx.x * WPB + w;

    __shared__ __align__(16) u64 sbuf[WPB][2][32];  // double-buffered s pairs
    __shared__ float2 mrow[WPB][Sn];                // (m, 1-m) per step

    // Stage mask row (warp-private region; no block sync needed)
    for (int i = c; i < Sn; i += 32) {
        float m = mask[b * Sn + i];
        mrow[w][i] = make_float2(m, 1.0f - m);
    }

    // E register tiles: EA[p] = (E[2p][2c], E[2p+1][2c]), EB for col 2c+1
    u64 EA[32], EB[32];
#pragma unroll
    for (int p = 0; p < 32; p++) {
        EA[p] = pk2(__expf(tr[(2 * p) * Tn + 2 * c]),
                    __expf(tr[(2 * p + 1) * Tn + 2 * c]));
        EB[p] = pk2(__expf(tr[(2 * p) * Tn + 2 * c + 1]),
                    __expf(tr[(2 * p + 1) * Tn + 2 * c + 1]));
    }

    // Emission stream: raw float2 loaded 8 steps ahead; exp'd at step top
    // (MUFU lat 16 << ~150 cyc until the tail consumes it)
    const float2* ep = (const float2*)(em + (size_t)b * Sn * Tn) + c;
    float2 eraw[8];
#pragma unroll
    for (int d = 0; d < 8; d++) eraw[d] = __ldg(ep + d * 32);

    u64 s    = pk2(1.0f, 1.0f);
    int offk = 0;
    __syncwarp();

    for (int tb = 0; tb < Sn; tb += 8) {
#pragma unroll
        for (int u = 0; u < 8; u++) {
            const int t   = tb + u;
            const int par = u & 1;

            // publish own pair
            sbuf[w][par][c] = s;

            // independent work rides through the sync window
            float2 mm = mrow[w][t];
            float2 er = eraw[u];
            u64 f = pk2(__expf(er.x), __expf(er.y));   // MUFU, used at tail
            if (t + 8 < Sn) eraw[u] = __ldg(ep + (size_t)(t + 8) * 32);

            __syncwarp();

            // matvec for both columns: 16 LDS.128, 64 FFMA2 (8 acc chains)
            const u64* sv = &sbuf[w][par][0];
            u64 a0 = 0, a1 = 0, a2 = 0, a3 = 0;
            u64 b0 = 0, b1 = 0, b2 = 0, b3 = 0;
            u64 v0pair;
#pragma unroll
            for (int p = 0; p < 32; p += 4) {
                ulonglong2 x = *(const ulonglong2*)&sv[p];
                ulonglong2 y = *(const ulonglong2*)&sv[p + 2];
                if (p == 0) v0pair = x.x;
                a0 = ffma2(x.x, EA[p + 0], a0);
                b0 = ffma2(x.x, EB[p + 0], b0);
                a1 = ffma2(x.y, EA[p + 1], a1);
                b1 = ffma2(x.y, EB[p + 1], b1);
                a2 = ffma2(y.x, EA[p + 2], a2);
                b2 = ffma2(y.x, EB[p + 2], b2);
                a3 = ffma2(y.y, EA[p + 3], a3);
                b3 = ffma2(y.y, EB[p + 3], b3);
            }
            u64 sa = fadd2(fadd2(a0, a1), fadd2(a2, a3));
            u64 sb = fadd2(fadd2(b0, b1), fadd2(b2, b3));
            float2 fa = upk(sa), fb2 = upk(sb);
            u64 qf = fmul2(pk2(fa.x + fa.y, fb2.x + fb2.y), f);

            // masked blend: s = m*qf + (1-m)*s
            u64 sn = ffma2(pk2(mm.y, mm.y), s, fmul2(pk2(mm.x, mm.x), qf));

            // renorm every 8 steps by 2^-ke, ke from exponent of s[0]
            // (v0pair.x = published s[0], uniform across lanes)
            if (u == 7) {
                int ke = ((__float_as_int(upk(v0pair).x) >> 23) & 0xff) - 127;
                offk += ke;
                float sc = __int_as_float((127 - ke) << 23);
                sn = fmul2(sn, pk2(sc, sc));
            }
            s = sn;
        }
    }

    // z[b] = offk*ln2 + log(sum_j s[j])
    float2 sp = upk(s);
    float x = sp.x + sp.y;
#pragma unroll
    for (int o = 16; o; o >>= 1)
        x += __shfl_xor_sync(0xffffffffu, x, o);
    if (lane == 0) {
        double z = (double)offk * 0.6931471805599453 + (double)logf(x);
        g_z[b] = (float)z;
    }
}

// ---------------------------------------------------------------------------
// out = -mean(z - score)
// ---------------------------------------------------------------------------
__global__ __launch_bounds__(Bn) void crf_final(float* __restrict__ out)
{
    __shared__ float red[Bn];
    const int tid = threadIdx.x;
    red[tid] = g_z[tid] - g_sc[tid];
    __syncthreads();
    for (int st = Bn / 2; st; st >>= 1) {
        if (tid < st) red[tid] += red[tid + st];
        __syncthreads();
    }
    if (tid == 0) out[0] = -red[0] / (float)Bn;
}

extern "C" void kernel_launch(void* const* d_in, const int* in_sizes, int n_in,
                              void* d_out, int out_size)
{
    const float* em   = (const float*)d_in[0];  // emissions [B,S,T] f32
    const int*   tags = (const int*)  d_in[1];  // tags [B,S] i32
    const float* mask = (const float*)d_in[2];  // mask [B,S] f32
    const float* tr   = (const float*)d_in[3];  // transitions [T,T] f32

    crf_fused<<<FWD_BLOCKS + GOLD_BLOCKS, 32 * WPB>>>(em, tags, mask, tr);
    crf_final<<<1, Bn>>>((float*)d_out);
}